// round 3
// baseline (speedup 1.0000x reference)
#include <cuda_runtime.h>
#include <cuda_bf16.h>
#include <cstdint>

#define DIMS   128
#define GAMMA  12.0f

// -------------------------------------------------------------------------
// Zero-init the output accumulator (d_out is poisoned to 0xAA by harness).
// Grid-stride over float4s.
// -------------------------------------------------------------------------
__global__ void zero_out_kernel(float4* __restrict__ out, int n4) {
    int i = blockIdx.x * blockDim.x + threadIdx.x;
    int stride = gridDim.x * blockDim.x;
    float4 z = make_float4(0.f, 0.f, 0.f, 0.f);
    for (; i < n4; i += stride) out[i] = z;
}

// -------------------------------------------------------------------------
// One warp per edge. Each lane owns 4 of the 128 dims (one float4).
//   trans = head + rel
//   dist  = || trans - tail ||_2   (warp shfl reduction)
//   score = sigmoid(gamma - dist)
//   out[dst] += score * trans      (red.global.add.v4.f32, no return)
// -------------------------------------------------------------------------
__global__ __launch_bounds__(256)
void transe_edge_kernel(const float* __restrict__ node_emb,
                        const float* __restrict__ edge_emb,
                        const int*   __restrict__ src,
                        const int*   __restrict__ dst,
                        float*       __restrict__ out,
                        int E) {
    const int warp = (blockIdx.x * blockDim.x + threadIdx.x) >> 5;
    const int lane = threadIdx.x & 31;
    if (warp >= E) return;

    const int s = __ldg(src + warp);
    const int d = __ldg(dst + warp);

    const float4* hrow = reinterpret_cast<const float4*>(node_emb + (size_t)s * DIMS);
    const float4* trow = reinterpret_cast<const float4*>(node_emb + (size_t)d * DIMS);
    const float4* erow = reinterpret_cast<const float4*>(edge_emb + (size_t)warp * DIMS);

    const float4 h = __ldg(hrow + lane);
    const float4 e = __ldg(erow + lane);
    const float4 t = __ldg(trow + lane);

    float4 tr;
    tr.x = h.x + e.x;
    tr.y = h.y + e.y;
    tr.z = h.z + e.z;
    tr.w = h.w + e.w;

    const float dx = tr.x - t.x;
    const float dy = tr.y - t.y;
    const float dz = tr.z - t.z;
    const float dw = tr.w - t.w;

    float ss = dx * dx + dy * dy + dz * dz + dw * dw;

    // warp reduction over 32 lanes -> full 128-dim sum of squares
    #pragma unroll
    for (int off = 16; off > 0; off >>= 1)
        ss += __shfl_xor_sync(0xffffffffu, ss, off);

    const float dist  = sqrtf(ss);
    const float score = 1.0f / (1.0f + __expf(dist - GAMMA));

    const float4 o4 = make_float4(score * tr.x, score * tr.y,
                                  score * tr.z, score * tr.w);

    float* outp = out + (size_t)d * DIMS + lane * 4;
    asm volatile("red.global.add.v4.f32 [%0], {%1, %2, %3, %4};"
                 :: "l"(outp), "f"(o4.x), "f"(o4.y), "f"(o4.z), "f"(o4.w)
                 : "memory");
}

// -------------------------------------------------------------------------
// Harness entry. Inputs (metadata order):
//   d_in[0] node_emb  float32 [N,128]
//   d_in[1] edge_emb  float32 [E,128]
//   d_in[2] src       int32   [E]
//   d_in[3] dst       int32   [E]
// d_out: float32 [N,128]
// -------------------------------------------------------------------------
extern "C" void kernel_launch(void* const* d_in, const int* in_sizes, int n_in,
                              void* d_out, int out_size) {
    const float* node_emb = (const float*)d_in[0];
    const float* edge_emb = (const float*)d_in[1];
    const int*   src      = (const int*)d_in[2];
    const int*   dst      = (const int*)d_in[3];
    float*       out      = (float*)d_out;

    const int E  = in_sizes[2];
    const int n4 = out_size / 4;   // number of float4s in output

    // 1) zero the accumulator
    {
        int threads = 256;
        int blocks  = (n4 + threads - 1) / threads;
        if (blocks > 8192) blocks = 8192;  // grid-stride
        zero_out_kernel<<<blocks, threads>>>((float4*)out, n4);
    }

    // 2) edge kernel: one warp per edge
    {
        int threads = 256;                         // 8 warps / block
        long long totalWarps = E;
        int blocks = (int)((totalWarps * 32 + threads - 1) / threads);
        transe_edge_kernel<<<blocks, threads>>>(node_emb, edge_emb, src, dst,
                                                out, E);
    }
}

// round 5
// speedup vs baseline: 1.0971x; 1.0971x over previous
#include <cuda_runtime.h>
#include <cuda_bf16.h>
#include <cstdint>

#define DIMS   128
#define GAMMA  12.0f

// -------------------------------------------------------------------------
// Zero-init the output accumulator (d_out is poisoned to 0xAA by harness).
// -------------------------------------------------------------------------
__global__ void zero_out_kernel(float4* __restrict__ out, int n4) {
    int i = blockIdx.x * blockDim.x + threadIdx.x;
    int stride = gridDim.x * blockDim.x;
    float4 z = make_float4(0.f, 0.f, 0.f, 0.f);
    for (; i < n4; i += stride) out[i] = z;
}

// L2 evict-last policy handle (sm_80+): full-fraction evict_last.
__device__ __forceinline__ uint64_t make_evict_last_policy() {
    uint64_t pol;
    asm("createpolicy.fractional.L2::evict_last.b64 %0, 1.0;" : "=l"(pol));
    return pol;
}

// node_emb gather: read-only, pin in L2 via cache-hint policy — the 51 MB
// node table plus the 51 MB accumulator fit in the 126 MB L2 as long as
// the edge stream doesn't evict them.
__device__ __forceinline__ float4 ldg_pin_l2(const float4* p, uint64_t pol) {
    float4 v;
    asm volatile("ld.global.nc.L2::cache_hint.v4.f32 {%0,%1,%2,%3}, [%4], %5;"
                 : "=f"(v.x), "=f"(v.y), "=f"(v.z), "=f"(v.w)
                 : "l"(p), "l"(pol));
    return v;
}

// edge_emb stream: touched exactly once -> evict-first at both levels.
__device__ __forceinline__ float4 ldg_stream(const float4* p) {
    float4 v;
    asm volatile("ld.global.cs.v4.f32 {%0,%1,%2,%3}, [%4];"
                 : "=f"(v.x), "=f"(v.y), "=f"(v.z), "=f"(v.w)
                 : "l"(p));
    return v;
}

// -------------------------------------------------------------------------
// One warp per edge. Each lane owns 4 of the 128 dims (one float4).
//   trans = head + rel
//   dist  = || trans - tail ||_2   (warp shfl reduction)
//   score = sigmoid(gamma - dist)
//   out[dst] += score * trans      (red.global.add.v4.f32, no return)
// -------------------------------------------------------------------------
__global__ __launch_bounds__(256)
void transe_edge_kernel(const float* __restrict__ node_emb,
                        const float* __restrict__ edge_emb,
                        const int*   __restrict__ src,
                        const int*   __restrict__ dst,
                        float*       __restrict__ out,
                        int E) {
    const int warp = (blockIdx.x * blockDim.x + threadIdx.x) >> 5;
    const int lane = threadIdx.x & 31;
    if (warp >= E) return;

    const uint64_t pol = make_evict_last_policy();

    const int s = __ldg(src + warp);
    const int d = __ldg(dst + warp);

    const float4* hrow = reinterpret_cast<const float4*>(node_emb + (size_t)s * DIMS);
    const float4* trow = reinterpret_cast<const float4*>(node_emb + (size_t)d * DIMS);
    const float4* erow = reinterpret_cast<const float4*>(edge_emb + (size_t)warp * DIMS);

    const float4 e = ldg_stream(erow + lane);        // stream: evict-first
    const float4 h = ldg_pin_l2(hrow + lane, pol);   // pin node table in L2
    const float4 t = ldg_pin_l2(trow + lane, pol);

    float4 tr;
    tr.x = h.x + e.x;
    tr.y = h.y + e.y;
    tr.z = h.z + e.z;
    tr.w = h.w + e.w;

    const float dx = tr.x - t.x;
    const float dy = tr.y - t.y;
    const float dz = tr.z - t.z;
    const float dw = tr.w - t.w;

    float ss = dx * dx + dy * dy + dz * dz + dw * dw;

    #pragma unroll
    for (int off = 16; off > 0; off >>= 1)
        ss += __shfl_xor_sync(0xffffffffu, ss, off);

    const float dist  = sqrtf(ss);
    const float score = 1.0f / (1.0f + __expf(dist - GAMMA));

    const float4 o4 = make_float4(score * tr.x, score * tr.y,
                                  score * tr.z, score * tr.w);

    float* outp = out + (size_t)d * DIMS + lane * 4;
    asm volatile("red.global.add.v4.f32 [%0], {%1, %2, %3, %4};"
                 :: "l"(outp), "f"(o4.x), "f"(o4.y), "f"(o4.z), "f"(o4.w)
                 : "memory");
}

// -------------------------------------------------------------------------
// Harness entry. Inputs (metadata order):
//   d_in[0] node_emb  float32 [N,128]
//   d_in[1] edge_emb  float32 [E,128]
//   d_in[2] src       int32   [E]
//   d_in[3] dst       int32   [E]
// d_out: float32 [N,128]
// -------------------------------------------------------------------------
extern "C" void kernel_launch(void* const* d_in, const int* in_sizes, int n_in,
                              void* d_out, int out_size) {
    const float* node_emb = (const float*)d_in[0];
    const float* edge_emb = (const float*)d_in[1];
    const int*   src      = (const int*)d_in[2];
    const int*   dst      = (const int*)d_in[3];
    float*       out      = (float*)d_out;

    const int E  = in_sizes[2];
    const int n4 = out_size / 4;

    {
        int threads = 256;
        int blocks  = (n4 + threads - 1) / threads;
        if (blocks > 8192) blocks = 8192;
        zero_out_kernel<<<blocks, threads>>>((float4*)out, n4);
    }

    {
        int threads = 256;  // 8 warps / block
        long long totalWarps = E;
        int blocks = (int)((totalWarps * 32 + threads - 1) / threads);
        transe_edge_kernel<<<blocks, threads>>>(node_emb, edge_emb, src, dst,
                                                out, E);
    }
}

// round 7
// speedup vs baseline: 1.1094x; 1.0113x over previous
#include <cuda_runtime.h>
#include <cuda_bf16.h>
#include <cstdint>

#define DIMS   128
#define GAMMA  12.0f

// -------------------------------------------------------------------------
// Zero-init the output accumulator (d_out is poisoned to 0xAA by harness).
// -------------------------------------------------------------------------
__global__ void zero_out_kernel(float4* __restrict__ out, int n4) {
    int i = blockIdx.x * blockDim.x + threadIdx.x;
    int stride = gridDim.x * blockDim.x;
    float4 z = make_float4(0.f, 0.f, 0.f, 0.f);
    for (; i < n4; i += stride) out[i] = z;
}

// L2 evict-last policy handle (sm_80+): full-fraction evict_last.
__device__ __forceinline__ uint64_t make_evict_last_policy() {
    uint64_t pol;
    asm("createpolicy.fractional.L2::evict_last.b64 %0, 1.0;" : "=l"(pol));
    return pol;
}

// node_emb gather: read-only, pin in L2 via cache-hint policy.
__device__ __forceinline__ float4 ldg_pin_l2(const float4* p, uint64_t pol) {
    float4 v;
    asm volatile("ld.global.nc.L2::cache_hint.v4.f32 {%0,%1,%2,%3}, [%4], %5;"
                 : "=f"(v.x), "=f"(v.y), "=f"(v.z), "=f"(v.w)
                 : "l"(p), "l"(pol));
    return v;
}

// edge_emb stream: touched exactly once -> evict-first at both levels.
__device__ __forceinline__ float4 ldg_stream(const float4* p) {
    float4 v;
    asm volatile("ld.global.cs.v4.f32 {%0,%1,%2,%3}, [%4];"
                 : "=f"(v.x), "=f"(v.y), "=f"(v.z), "=f"(v.w)
                 : "l"(p));
    return v;
}

// -------------------------------------------------------------------------
// 8 lanes per edge (4 edges per warp). Each lane owns 16 dims as 4
// interleaved float4s: load i covers dims [i*32, i*32+32), lane gl takes
// float4 #(i*8+gl) -> every load instruction is a contiguous 128B segment
// per edge group. 12 independent loads per thread (MLP=12) to cover
// L2/DRAM latency; 3-step shfl reduction within the 8-lane group.
// -------------------------------------------------------------------------
__global__ __launch_bounds__(256)
void transe_edge_kernel(const float* __restrict__ node_emb,
                        const float* __restrict__ edge_emb,
                        const int*   __restrict__ src,
                        const int*   __restrict__ dst,
                        float*       __restrict__ out,
                        int E) {
    const int tid  = blockIdx.x * blockDim.x + threadIdx.x;
    const int eidx = tid >> 3;     // edge index: 8 lanes per edge
    const int gl   = tid & 7;      // lane within the 8-lane group
    if (eidx >= E) return;

    const uint64_t pol = make_evict_last_policy();

    const int s = __ldg(src + eidx);
    const int d = __ldg(dst + eidx);

    const float4* hrow = reinterpret_cast<const float4*>(node_emb + (size_t)s   * DIMS);
    const float4* trow = reinterpret_cast<const float4*>(node_emb + (size_t)d   * DIMS);
    const float4* erow = reinterpret_cast<const float4*>(edge_emb + (size_t)eidx * DIMS);

    // Issue all 12 loads up front -> deep MLP.
    float4 e4[4], h4[4], t4[4];
    #pragma unroll
    for (int i = 0; i < 4; i++) e4[i] = ldg_stream(erow + (i * 8 + gl));
    #pragma unroll
    for (int i = 0; i < 4; i++) h4[i] = ldg_pin_l2(hrow + (i * 8 + gl), pol);
    #pragma unroll
    for (int i = 0; i < 4; i++) t4[i] = ldg_pin_l2(trow + (i * 8 + gl), pol);

    float4 tr[4];
    float ss = 0.0f;
    #pragma unroll
    for (int i = 0; i < 4; i++) {
        tr[i].x = h4[i].x + e4[i].x;
        tr[i].y = h4[i].y + e4[i].y;
        tr[i].z = h4[i].z + e4[i].z;
        tr[i].w = h4[i].w + e4[i].w;
        const float dx = tr[i].x - t4[i].x;
        const float dy = tr[i].y - t4[i].y;
        const float dz = tr[i].z - t4[i].z;
        const float dw = tr[i].w - t4[i].w;
        ss += dx * dx + dy * dy + dz * dz + dw * dw;
    }

    // Reduce across the 8-lane group (xor offsets < 8 stay in-group).
    ss += __shfl_xor_sync(0xffffffffu, ss, 1);
    ss += __shfl_xor_sync(0xffffffffu, ss, 2);
    ss += __shfl_xor_sync(0xffffffffu, ss, 4);

    const float dist  = sqrtf(ss);
    const float score = 1.0f / (1.0f + __expf(dist - GAMMA));

    float* outbase = out + (size_t)d * DIMS;
    #pragma unroll
    for (int i = 0; i < 4; i++) {
        float* outp = outbase + (i * 8 + gl) * 4;
        asm volatile("red.global.add.v4.f32 [%0], {%1, %2, %3, %4};"
                     :: "l"(outp),
                        "f"(score * tr[i].x), "f"(score * tr[i].y),
                        "f"(score * tr[i].z), "f"(score * tr[i].w)
                     : "memory");
    }
}

// -------------------------------------------------------------------------
// Harness entry. Inputs (metadata order):
//   d_in[0] node_emb  float32 [N,128]
//   d_in[1] edge_emb  float32 [E,128]
//   d_in[2] src       int32   [E]
//   d_in[3] dst       int32   [E]
// d_out: float32 [N,128]
// -------------------------------------------------------------------------
extern "C" void kernel_launch(void* const* d_in, const int* in_sizes, int n_in,
                              void* d_out, int out_size) {
    const float* node_emb = (const float*)d_in[0];
    const float* edge_emb = (const float*)d_in[1];
    const int*   src      = (const int*)d_in[2];
    const int*   dst      = (const int*)d_in[3];
    float*       out      = (float*)d_out;

    const int E  = in_sizes[2];
    const int n4 = out_size / 4;

    {
        int threads = 256;
        int blocks  = (n4 + threads - 1) / threads;
        if (blocks > 8192) blocks = 8192;
        zero_out_kernel<<<blocks, threads>>>((float4*)out, n4);
    }

    {
        int threads = 256;  // 32 edges per block (8 lanes/edge)
        long long totalThreads = (long long)E * 8;
        int blocks = (int)((totalThreads + threads - 1) / threads);
        transe_edge_kernel<<<blocks, threads>>>(node_emb, edge_emb, src, dst,
                                                out, E);
    }
}

// round 8
// speedup vs baseline: 1.3151x; 1.1854x over previous
#include <cuda_runtime.h>
#include <cuda_bf16.h>
#include <cstdint>

#define DIMS   128
#define GAMMA  12.0f

// L2 evict-last policy handle (sm_80+): full-fraction evict_last.
__device__ __forceinline__ uint64_t make_evict_last_policy() {
    uint64_t pol;
    asm("createpolicy.fractional.L2::evict_last.b64 %0, 1.0;" : "=l"(pol));
    return pol;
}

// -------------------------------------------------------------------------
// Zero-init the output accumulator with evict_last policy: establishes the
// 51 MB accumulator as L2-resident before the edge kernel's atomics hit it.
// -------------------------------------------------------------------------
__global__ void zero_out_kernel(float4* __restrict__ out, int n4) {
    const uint64_t pol = make_evict_last_policy();
    int i = blockIdx.x * blockDim.x + threadIdx.x;
    int stride = gridDim.x * blockDim.x;
    for (; i < n4; i += stride) {
        asm volatile("st.global.L2::cache_hint.v4.f32 [%0], {%1,%2,%3,%4}, %5;"
                     :: "l"(out + i), "f"(0.f), "f"(0.f), "f"(0.f), "f"(0.f),
                        "l"(pol)
                     : "memory");
    }
}

// node_emb gather: read-only, pin in L2 via cache-hint policy.
__device__ __forceinline__ float4 ldg_pin_l2(const float4* p, uint64_t pol) {
    float4 v;
    asm volatile("ld.global.nc.L2::cache_hint.v4.f32 {%0,%1,%2,%3}, [%4], %5;"
                 : "=f"(v.x), "=f"(v.y), "=f"(v.z), "=f"(v.w)
                 : "l"(p), "l"(pol));
    return v;
}

// edge_emb stream: touched exactly once -> evict-first at both levels.
__device__ __forceinline__ float4 ldg_stream(const float4* p) {
    float4 v;
    asm volatile("ld.global.cs.v4.f32 {%0,%1,%2,%3}, [%4];"
                 : "=f"(v.x), "=f"(v.y), "=f"(v.z), "=f"(v.w)
                 : "l"(p));
    return v;
}

// -------------------------------------------------------------------------
// 8 lanes per edge (4 edges per warp). Each lane owns 16 dims as 4
// interleaved float4s. 12 independent loads per thread; 3-step shfl
// reduction within the 8-lane group. Atomics carry the evict_last policy
// so accumulator lines stay L2-resident against the edge stream.
// -------------------------------------------------------------------------
__global__ __launch_bounds__(256)
void transe_edge_kernel(const float* __restrict__ node_emb,
                        const float* __restrict__ edge_emb,
                        const int*   __restrict__ src,
                        const int*   __restrict__ dst,
                        float*       __restrict__ out,
                        int E) {
    const int tid  = blockIdx.x * blockDim.x + threadIdx.x;
    const int eidx = tid >> 3;     // edge index: 8 lanes per edge
    const int gl   = tid & 7;      // lane within the 8-lane group
    if (eidx >= E) return;

    const uint64_t pol = make_evict_last_policy();

    const int s = __ldg(src + eidx);
    const int d = __ldg(dst + eidx);

    const float4* hrow = reinterpret_cast<const float4*>(node_emb + (size_t)s    * DIMS);
    const float4* trow = reinterpret_cast<const float4*>(node_emb + (size_t)d    * DIMS);
    const float4* erow = reinterpret_cast<const float4*>(edge_emb + (size_t)eidx * DIMS);

    // Issue all 12 loads up front -> deep MLP.
    float4 e4[4], h4[4], t4[4];
    #pragma unroll
    for (int i = 0; i < 4; i++) e4[i] = ldg_stream(erow + (i * 8 + gl));
    #pragma unroll
    for (int i = 0; i < 4; i++) h4[i] = ldg_pin_l2(hrow + (i * 8 + gl), pol);
    #pragma unroll
    for (int i = 0; i < 4; i++) t4[i] = ldg_pin_l2(trow + (i * 8 + gl), pol);

    float4 tr[4];
    float ss = 0.0f;
    #pragma unroll
    for (int i = 0; i < 4; i++) {
        tr[i].x = h4[i].x + e4[i].x;
        tr[i].y = h4[i].y + e4[i].y;
        tr[i].z = h4[i].z + e4[i].z;
        tr[i].w = h4[i].w + e4[i].w;
        const float dx = tr[i].x - t4[i].x;
        const float dy = tr[i].y - t4[i].y;
        const float dz = tr[i].z - t4[i].z;
        const float dw = tr[i].w - t4[i].w;
        ss += dx * dx + dy * dy + dz * dz + dw * dw;
    }

    // Reduce across the 8-lane group (xor offsets < 8 stay in-group).
    ss += __shfl_xor_sync(0xffffffffu, ss, 1);
    ss += __shfl_xor_sync(0xffffffffu, ss, 2);
    ss += __shfl_xor_sync(0xffffffffu, ss, 4);

    const float dist  = sqrtf(ss);
    const float score = 1.0f / (1.0f + __expf(dist - GAMMA));

    float* outbase = out + (size_t)d * DIMS;
    #pragma unroll
    for (int i = 0; i < 4; i++) {
        float* outp = outbase + (i * 8 + gl) * 4;
        asm volatile("red.global.L2::cache_hint.add.v4.f32 [%0], {%1, %2, %3, %4}, %5;"
                     :: "l"(outp),
                        "f"(score * tr[i].x), "f"(score * tr[i].y),
                        "f"(score * tr[i].z), "f"(score * tr[i].w),
                        "l"(pol)
                     : "memory");
    }
}

// -------------------------------------------------------------------------
// Harness entry. Inputs (metadata order):
//   d_in[0] node_emb  float32 [N,128]
//   d_in[1] edge_emb  float32 [E,128]
//   d_in[2] src       int32   [E]
//   d_in[3] dst       int32   [E]
// d_out: float32 [N,128]
// -------------------------------------------------------------------------
extern "C" void kernel_launch(void* const* d_in, const int* in_sizes, int n_in,
                              void* d_out, int out_size) {
    const float* node_emb = (const float*)d_in[0];
    const float* edge_emb = (const float*)d_in[1];
    const int*   src      = (const int*)d_in[2];
    const int*   dst      = (const int*)d_in[3];
    float*       out      = (float*)d_out;

    const int E  = in_sizes[2];
    const int n4 = out_size / 4;

    {
        int threads = 256;
        int blocks  = (n4 + threads - 1) / threads;
        if (blocks > 8192) blocks = 8192;
        zero_out_kernel<<<blocks, threads>>>((float4*)out, n4);
    }

    {
        int threads = 256;  // 32 edges per block (8 lanes/edge)
        long long totalThreads = (long long)E * 8;
        int blocks = (int)((totalThreads + threads - 1) / threads);
        transe_edge_kernel<<<blocks, threads>>>(node_emb, edge_emb, src, dst,
                                                out, E);
    }
}